// round 1
// baseline (speedup 1.0000x reference)
#include <cuda_runtime.h>
#include <cuda_bf16.h>
#include <cstdint>

// Problem: out[b,o,{re,im}] = complex(x) @ complex(w)^T  (no conj)
// Reformulated as single real GEMM  C[M,N] = A[M,K] * B'[N,K]^T
//   M = 4096 (batch), K = 4096 (= 2*IN), N = 4096 (= 2*OUT)
//   A = [X_re | X_im]
//   B'[n]       = [ W_re[n],  -W_im[n] ]   (n < 2048  -> out_re)
//   B'[n+2048]  = [ W_im[n],   W_re[n] ]   (          -> out_im)
// fp32 accuracy via 3-term bf16 split: C = Ah*Bh + Ah*Bl + Al*Bh (fp32 accum).

static constexpr int M = 4096;
static constexpr int N = 4096;
static constexpr int K = 4096;
static constexpr int INF = 2048;
static constexpr int OUTF = 2048;

static constexpr int BM = 128;
static constexpr int BN = 128;
static constexpr int BK = 32;
static constexpr int LDS = BK + 8;        // 40 bf16 = 80B row (conflict-free ldmatrix)
static constexpr int TILE_A = BM * LDS;   // 5120 elems
static constexpr int TILE_B = BN * LDS;   // 5120 elems
static constexpr int SMEM_BYTES = (2 * TILE_A * 2 + 2 * TILE_B * 2) * 2; // 81920 B

// Scratch (static device globals — allowed; runtime alloc is not)
__device__ __nv_bfloat16 g_Ahi[(size_t)M * K];
__device__ __nv_bfloat16 g_Alo[(size_t)M * K];
__device__ __nv_bfloat16 g_Bhi[(size_t)N * K];
__device__ __nv_bfloat16 g_Blo[(size_t)N * K];

// ---------------------------------------------------------------------------
// Prep kernels: build split bf16 operands
// ---------------------------------------------------------------------------
__global__ void prep_A(const float* __restrict__ xre, const float* __restrict__ xim) {
    int idx = blockIdx.x * blockDim.x + threadIdx.x;    // over M*K
    int k = idx & (K - 1);
    int b = idx >> 12;
    float v = (k < INF) ? xre[b * INF + k] : xim[b * INF + (k - INF)];
    __nv_bfloat16 hi = __float2bfloat16(v);
    g_Ahi[idx] = hi;
    g_Alo[idx] = __float2bfloat16(v - __bfloat162float(hi));
}

__global__ void prep_B(const float* __restrict__ wre, const float* __restrict__ wim) {
    int idx = blockIdx.x * blockDim.x + threadIdx.x;    // over N*K
    int k = idx & (K - 1);
    int n = idx >> 12;
    float v;
    if (n < OUTF) {
        v = (k < INF) ? wre[n * INF + k] : -wim[n * INF + (k - INF)];
    } else {
        int o = n - OUTF;
        v = (k < INF) ? wim[o * INF + k] : wre[o * INF + (k - INF)];
    }
    __nv_bfloat16 hi = __float2bfloat16(v);
    g_Bhi[idx] = hi;
    g_Blo[idx] = __float2bfloat16(v - __bfloat162float(hi));
}

// ---------------------------------------------------------------------------
// MMA / ldmatrix / cp.async helpers
// ---------------------------------------------------------------------------
__device__ __forceinline__ void cp_async16(uint32_t saddr, const void* g) {
    asm volatile("cp.async.cg.shared.global [%0], [%1], 16;" :: "r"(saddr), "l"(g));
}
__device__ __forceinline__ void cp_commit() { asm volatile("cp.async.commit_group;"); }
__device__ __forceinline__ void cp_wait1()  { asm volatile("cp.async.wait_group 1;"); }

__device__ __forceinline__ void ldm_x4(uint32_t* r, uint32_t saddr) {
    asm volatile("ldmatrix.sync.aligned.m8n8.x4.shared.b16 {%0,%1,%2,%3}, [%4];"
                 : "=r"(r[0]), "=r"(r[1]), "=r"(r[2]), "=r"(r[3]) : "r"(saddr));
}
__device__ __forceinline__ void mma16816(float* c, const uint32_t* a, const uint32_t* b) {
    asm volatile("mma.sync.aligned.m16n8k16.row.col.f32.bf16.bf16.f32 "
                 "{%0,%1,%2,%3}, {%4,%5,%6,%7}, {%8,%9}, {%0,%1,%2,%3};"
                 : "+f"(c[0]), "+f"(c[1]), "+f"(c[2]), "+f"(c[3])
                 : "r"(a[0]), "r"(a[1]), "r"(a[2]), "r"(a[3]),
                   "r"(b[0]), "r"(b[1]));
}

// ---------------------------------------------------------------------------
// GEMM: 128x128 CTA tile, BK=32, 8 warps in 2x4 grid, each warp 64x32.
// 3 MMA products per fragment pair (hi*hi, hi*lo, lo*hi), fp32 accumulators.
// ---------------------------------------------------------------------------
__global__ void __launch_bounds__(256) gemm_split3(float* __restrict__ out) {
    extern __shared__ __align__(16) __nv_bfloat16 smem[];
    __nv_bfloat16* sAhi = smem;
    __nv_bfloat16* sAlo = sAhi + 2 * TILE_A;
    __nv_bfloat16* sBhi = sAlo + 2 * TILE_A;
    __nv_bfloat16* sBlo = sBhi + 2 * TILE_B;

    const int tid  = threadIdx.x;
    const int lane = tid & 31;
    const int warp = tid >> 5;
    const int wm = warp >> 2;     // 0..1
    const int wn = warp & 3;      // 0..3
    const int bm0 = blockIdx.y * BM;
    const int bn0 = blockIdx.x * BN;

    float acc[4][4][4];
#pragma unroll
    for (int i = 0; i < 4; i++)
#pragma unroll
        for (int j = 0; j < 4; j++)
#pragma unroll
            for (int q = 0; q < 4; q++) acc[i][j][q] = 0.f;

    // 512 16B-chunks per 128x32 tile; thread t loads chunks t and t+256.
    auto load_tile = [&](int buf, int k0) {
#pragma unroll
        for (int rep = 0; rep < 2; rep++) {
            int ch  = tid + rep * 256;
            int row = ch >> 2;
            int col = (ch & 3) * 8;
            size_t goffA = (size_t)(bm0 + row) * K + k0 + col;
            size_t goffB = (size_t)(bn0 + row) * K + k0 + col;
            int soff = buf * TILE_A + row * LDS + col;
            cp_async16((uint32_t)__cvta_generic_to_shared(sAhi + soff), g_Ahi + goffA);
            cp_async16((uint32_t)__cvta_generic_to_shared(sAlo + soff), g_Alo + goffA);
            cp_async16((uint32_t)__cvta_generic_to_shared(sBhi + soff), g_Bhi + goffB);
            cp_async16((uint32_t)__cvta_generic_to_shared(sBlo + soff), g_Blo + goffB);
        }
    };

    load_tile(0, 0);
    cp_commit();

    const int NKT = K / BK;   // 128
    for (int kt = 0; kt < NKT; kt++) {
        int cur = kt & 1;
        if (kt + 1 < NKT) load_tile(cur ^ 1, (kt + 1) * BK);
        cp_commit();
        cp_wait1();
        __syncthreads();

#pragma unroll
        for (int ks = 0; ks < 2; ks++) {
            const int kk = ks * 16;

            // A fragments (hi & lo): 4 m-frags of 16 rows each
            uint32_t ahi[4][4], alo[4][4];
            {
                int row = wm * 64 + (lane & 15);
                int col = kk + ((lane >> 4) << 3);
#pragma unroll
                for (int im = 0; im < 4; im++) {
                    int soff = cur * TILE_A + (row + im * 16) * LDS + col;
                    ldm_x4(ahi[im], (uint32_t)__cvta_generic_to_shared(sAhi + soff));
                    ldm_x4(alo[im], (uint32_t)__cvta_generic_to_shared(sAlo + soff));
                }
            }

            // B fragments (hi & lo): 4 n-frags of 8 rows, loaded as 2 x4-ldmatrix
            uint32_t bhi[4][2], blo[4][2];
            {
                int mset = lane >> 3;                 // which 8x8 matrix this lane addresses
                int nrow_in = (lane & 7) + ((mset >> 1) << 3);
                int col = kk + ((mset & 1) << 3);
#pragma unroll
                for (int ip = 0; ip < 2; ip++) {
                    int nrow = wn * 32 + ip * 16 + nrow_in;
                    int soff = cur * TILE_B + nrow * LDS + col;
                    uint32_t r[4];
                    ldm_x4(r, (uint32_t)__cvta_generic_to_shared(sBhi + soff));
                    bhi[ip * 2][0] = r[0]; bhi[ip * 2][1] = r[1];
                    bhi[ip * 2 + 1][0] = r[2]; bhi[ip * 2 + 1][1] = r[3];
                    ldm_x4(r, (uint32_t)__cvta_generic_to_shared(sBlo + soff));
                    blo[ip * 2][0] = r[0]; blo[ip * 2][1] = r[1];
                    blo[ip * 2 + 1][0] = r[2]; blo[ip * 2 + 1][1] = r[3];
                }
            }

#pragma unroll
            for (int im = 0; im < 4; im++) {
#pragma unroll
                for (int in = 0; in < 4; in++) {
                    mma16816(acc[im][in], ahi[im], bhi[in]);
                    mma16816(acc[im][in], ahi[im], blo[in]);
                    mma16816(acc[im][in], alo[im], bhi[in]);
                }
            }
        }
        __syncthreads();
    }

    // Epilogue: C[m, n] -> out[m, n & 2047, n >> 11]
    const int gr = lane >> 2;
    const int gc = (lane & 3) << 1;
#pragma unroll
    for (int im = 0; im < 4; im++) {
#pragma unroll
        for (int in = 0; in < 4; in++) {
            int m0 = bm0 + wm * 64 + im * 16 + gr;
            int n0 = bn0 + wn * 32 + in * 8 + gc;
            int c = n0 >> 11;
            int o = n0 & (OUTF - 1);
            out[((size_t)m0 * OUTF + o) * 2 + c]           = acc[im][in][0];
            out[((size_t)m0 * OUTF + o + 1) * 2 + c]       = acc[im][in][1];
            out[((size_t)(m0 + 8) * OUTF + o) * 2 + c]     = acc[im][in][2];
            out[((size_t)(m0 + 8) * OUTF + o + 1) * 2 + c] = acc[im][in][3];
        }
    }
}

// ---------------------------------------------------------------------------
extern "C" void kernel_launch(void* const* d_in, const int* in_sizes, int n_in,
                              void* d_out, int out_size) {
    const float* x_re = (const float*)d_in[0];
    const float* x_im = (const float*)d_in[1];
    const float* w_re = (const float*)d_in[2];
    const float* w_im = (const float*)d_in[3];
    float* out = (float*)d_out;

    cudaFuncSetAttribute(gemm_split3, cudaFuncAttributeMaxDynamicSharedMemorySize,
                         SMEM_BYTES);

    prep_A<<<(M * K) / 256, 256>>>(x_re, x_im);
    prep_B<<<(N * K) / 256, 256>>>(w_re, w_im);

    dim3 grid(N / BN, M / BM);
    gemm_split3<<<grid, 256, SMEM_BYTES>>>(out);
}